// round 15
// baseline (speedup 1.0000x reference)
#include <cuda_runtime.h>

// Problem constants
#define KK 4
#define MM 32
#define DD 2048
#define TT 128
#define TTILE 16          // t-columns per CTA (64B of each 128B line)
#define NTHREADS 1024
#define NTILES 1024       // 128 km * 8 t-blocks

typedef unsigned long long u64;

// smem (u64 units):
//  xch: 16 t-buffers * 1025 u64 (2050 floats, odd u64 stride -> conflict-free)
//  T1/T3: phase-1 packed (d, d+32); T2/TB: phase-2 packed (d, d+1024), q-split
#define XSU 1025
#define XCH_U64 (16 * XSU)         // 16400
#define T1O (XCH_U64)
#define T3O (T1O + 1024)
#define T2O (T3O + 1024)
#define TBO (T2O + 1200)
#define SMEM_U64 (TBO + 1200)      // 20848
#define SMEM_BYTES (SMEM_U64 * 8)  // 166784

#define HNORM 0.022097086912079608f   // 1/sqrt(2048), folded per diagonal

// ---- packed f32x2 helpers (sm_103a) ----
__device__ __forceinline__ u64 addx2(u64 a, u64 b) {
    u64 r; asm("add.rn.f32x2 %0,%1,%2;" : "=l"(r) : "l"(a), "l"(b)); return r;
}
__device__ __forceinline__ u64 subx2(u64 a, u64 b) {
    u64 r; asm("sub.rn.f32x2 %0,%1,%2;" : "=l"(r) : "l"(a), "l"(b)); return r;
}
__device__ __forceinline__ u64 mulx2(u64 a, u64 b) {
    u64 r; asm("mul.rn.f32x2 %0,%1,%2;" : "=l"(r) : "l"(a), "l"(b)); return r;
}
__device__ __forceinline__ u64 pk(float lo, float hi) {
    u64 r; asm("mov.b64 %0,{%1,%2};" : "=l"(r) : "f"(lo), "f"(hi)); return r;
}
__device__ __forceinline__ void upk(float& lo, float& hi, u64 v) {
    asm("mov.b64 {%0,%1},%2;" : "=f"(lo), "=f"(hi) : "l"(v));
}

#define BFLY(A, B) { u64 _a = (A), _b = (B); (A) = addx2(_a, _b); (B) = subx2(_a, _b); }

// 4 local stages over 16-reg array (reg-index bits 0..3)
#define LOCAL4(y) \
    { _Pragma("unroll") for (int s = 1; s < 16; s <<= 1) { \
        _Pragma("unroll") for (int j = 0; j < 16; ++j) \
            if ((j & s) == 0) BFLY(y[j], y[j | s]); } }

// cross-thread stage (d0 bit = lane bit 4), phase-1 only
#define CROSS(y, q) \
    { _Pragma("unroll") for (int i = 0; i < 16; ++i) { \
        u64 _o = __shfl_xor_sync(0xffffffffu, y[i], 16); \
        y[i] = (q) ? subx2(_o, y[i]) : addx2(y[i], _o); } }

// intra-register stage (pack-bit butterfly)
#define INTRA(y) \
    { _Pragma("unroll") for (int i = 0; i < 16; ++i) { \
        float _lo, _hi; upk(_lo, _hi, y[i]); \
        y[i] = pk(_lo + _hi, _lo - _hi); } }

__global__ __launch_bounds__(NTHREADS, 1)
void spinner_main_kernel(const float* __restrict__ z,
                         const float* __restrict__ d1,
                         const float* __restrict__ d2,
                         const float* __restrict__ d3,
                         const float* __restrict__ bia,
                         const float* __restrict__ sldj_in,
                         float* __restrict__ out)
{
    extern __shared__ u64 sm[];
    const int tid = threadIdx.x;
    const int bid = blockIdx.x;

    // ---- block 0: sldj ----
    if (bid == 0) {
        float* red = (float*)sm;
        float s = 0.f;
        #pragma unroll
        for (int r = 0; r < 2; ++r) {
            int i = tid + r * NTHREADS;
            s += logf(fabsf(d1[i])) + logf(fabsf(d2[i])) + logf(fabsf(d3[i]));
        }
        red[tid] = s;
        __syncthreads();
        #pragma unroll
        for (int w = 512; w > 0; w >>= 1) {
            if (tid < w) red[tid] += red[tid + w];
            __syncthreads();
        }
        float ld = red[0];
        if (tid < KK * MM)
            out[(size_t)KK * MM * DD * TT + tid] = sldj_in[tid] + ld;
        return;
    }

    float* xcf = (float*)sm;                 // exchange, float-granular

    const int tile = bid - 1;
    const int km = tile >> 3;
    const int t0 = (tile & 7) * TTILE;
    const int t  = tid & 15;
    const int q  = (tid >> 4) & 1;
    const int u  = tid >> 5;                 // 0..31

    const float* zin = z + (size_t)km * (DD * TT) + (t0 + t);
    u64 y[16];

    // ---- PREFETCH raw z, streaming (phase-1: h=u, dlow = 2i+q, pack +32) ----
    #pragma unroll
    for (int i = 0; i < 16; ++i) {
        int dlo = u * 64 + 2 * i + q;
        y[i] = pk(__ldcs(zin + (size_t)dlo * TT),
                  __ldcs(zin + (size_t)(dlo + 32) * TT));
    }

    // ---- stage scale tables (overlaps z-load latency) ----
    {
        int c = tid >> 5, p = tid & 31;
        int d = c * 64 + p;
        sm[T1O + tid] = pk(d1[d] * HNORM, d1[d + 32] * HNORM);
        sm[T3O + tid] = pk(d3[d] * HNORM, d3[d + 32] * HNORM);
        int q_ = tid >> 9, r_ = tid & 511;
        int u_ = r_ >> 4, k_ = r_ & 15;
        int dl = u_ + 32 * q_;
        sm[T2O + q_ * 600 + r_] = pk(d2[k_ * 64 + dl] * HNORM,
                                     d2[(k_ + 16) * 64 + dl] * HNORM);
        sm[TBO + q_ * 600 + r_] = pk(bia[k_ * 64 + dl],
                                     bia[(k_ + 16) * 64 + dl]);
    }
    __syncthreads();

    // ---- d1 scale ----
    #pragma unroll
    for (int i = 0; i < 16; ++i)
        y[i] = mulx2(y[i], sm[T1O + u * 32 + 2 * i + q]);

    // ---- FWHT #1 low (d0..d5): CROSS(d0) + LOCAL4(d1-d4) + INTRA(d5) ----
    CROSS(y, q); LOCAL4(y); INTRA(y);

    // exchange addressing
    float* xt = xcf + t * 2050;
    const int sq   = (2 * (u & 15) + (u >> 4)) ^ q;  // sigma0(u) ^ parity(dlow)
    const int dlow = u + 32 * q;                     // phase-2 owned d-low
    const int par  = u & 1;                          // parity(dlow) in phase-2
    float* xr = xt + dlow * 32;

    // E1-write: float (dlow=2i+q, h=u) and (dlow+32, h=u)
    #pragma unroll
    for (int i = 0; i < 16; ++i) {
        float lo, hi; upk(lo, hi, y[i]);
        xt[(2 * i + q) * 32 + sq]        = lo;
        xt[(2 * i + q + 32) * 32 + sq]   = hi;
    }
    __syncthreads();
    // E1-read: LDS.64 pairs (h=k, h=k+16) at own dlow (parity swap)
    #pragma unroll
    for (int k = 0; k < 16; ++k) {
        float2 v = *(const float2*)(xr + 2 * k);
        y[k] = par ? pk(v.y, v.x) : pk(v.x, v.y);
    }

    // ---- FWHT #1 high (d6..d10): LOCAL4(d6-d9) + INTRA(d10) ----
    LOCAL4(y); INTRA(y);

    // ---- d2 scale (phase-2 pack (d, d+1024)) ----
    {
        const u64* t2 = sm + T2O + q * 600 + u * 16;
        #pragma unroll
        for (int k = 0; k < 16; ++k) y[k] = mulx2(y[k], t2[k]);
    }

    // ---- FWHT #2 high ----
    INTRA(y); LOCAL4(y);

    // E2-write: STS.64 back to own E1-read slots (no pre-sync needed)
    #pragma unroll
    for (int k = 0; k < 16; ++k) {
        u64 v = y[k];
        if (par) v = (v >> 32) | (v << 32);
        *(u64*)(xr + 2 * k) = v;
    }
    __syncthreads();
    // E2-read: two LDS.32 per reg (phase-1 pattern)
    #pragma unroll
    for (int i = 0; i < 16; ++i) {
        float lo = xt[(2 * i + q) * 32 + sq];
        float hi = xt[(2 * i + q + 32) * 32 + sq];
        y[i] = pk(lo, hi);
    }

    // ---- FWHT #2 low ----
    INTRA(y); LOCAL4(y); CROSS(y, q);

    // ---- d3 scale ----
    #pragma unroll
    for (int i = 0; i < 16; ++i)
        y[i] = mulx2(y[i], sm[T3O + u * 32 + 2 * i + q]);

    // ---- FWHT #3 low ----
    CROSS(y, q); LOCAL4(y); INTRA(y);

    // E3-write (own E2-read slots: no pre-sync)
    #pragma unroll
    for (int i = 0; i < 16; ++i) {
        float lo, hi; upk(lo, hi, y[i]);
        xt[(2 * i + q) * 32 + sq]        = lo;
        xt[(2 * i + q + 32) * 32 + sq]   = hi;
    }
    __syncthreads();
    // E3-read
    #pragma unroll
    for (int k = 0; k < 16; ++k) {
        float2 v = *(const float2*)(xr + 2 * k);
        y[k] = par ? pk(v.y, v.x) : pk(v.x, v.y);
    }

    // ---- FWHT #3 high ----
    LOCAL4(y); INTRA(y);

    // ---- bias + store, streaming (rows k*64+dlow and (k+16)*64+dlow) ----
    {
        float* zout = out + (size_t)km * (DD * TT) + (t0 + t);
        const u64* tb = sm + TBO + q * 600 + u * 16;
        #pragma unroll
        for (int k = 0; k < 16; ++k) {
            u64 r_ = addx2(y[k], tb[k]);
            float lo, hi; upk(lo, hi, r_);
            __stcs(zout + (size_t)(k * 64 + dlow) * TT, lo);
            __stcs(zout + (size_t)((k + 16) * 64 + dlow) * TT, hi);
        }
    }
}

extern "C" void kernel_launch(void* const* d_in, const int* in_sizes, int n_in,
                              void* d_out, int out_size)
{
    (void)in_sizes; (void)n_in; (void)out_size;
    const float* z    = (const float*)d_in[0];
    const float* d1   = (const float*)d_in[1];
    const float* d2   = (const float*)d_in[2];
    const float* d3   = (const float*)d_in[3];
    const float* bia  = (const float*)d_in[4];
    const float* sldj = (const float*)d_in[5];
    float* out = (float*)d_out;

    cudaFuncSetAttribute(spinner_main_kernel,
                         cudaFuncAttributeMaxDynamicSharedMemorySize, SMEM_BYTES);

    // grid: 1 sldj block + 1024 tile blocks
    spinner_main_kernel<<<NTILES + 1, NTHREADS, SMEM_BYTES>>>(
        z, d1, d2, d3, bia, sldj, out);
}

// round 16
// speedup vs baseline: 1.0797x; 1.0797x over previous
#include <cuda_runtime.h>

// Problem constants
#define KK 4
#define MM 32
#define DD 2048
#define TT 128
#define TTILE 16          // t-columns per CTA (64B of each 128B line)
#define NTHREADS 1024
#define NTILES 1024       // 128 km * 8 t-blocks

typedef unsigned long long u64;

// smem (u64 units):
//  xch: 16 t-buffers * 1025 u64 (2050 floats, odd u64 stride -> conflict-free)
//  T1/T3: phase-1 packed (d, d+32); T2/TB: phase-2 packed (d, d+1024), q-split
#define XSU 1025
#define XCH_U64 (16 * XSU)         // 16400
#define T1O (XCH_U64)
#define T3O (T1O + 1024)
#define T2O (T3O + 1024)
#define TBO (T2O + 1200)
#define SMEM_U64 (TBO + 1200)      // 20848
#define SMEM_BYTES (SMEM_U64 * 8)  // 166784

#define HNORM 0.022097086912079608f   // 1/sqrt(2048), folded per diagonal

// ---- packed f32x2 helpers (sm_103a) ----
__device__ __forceinline__ u64 addx2(u64 a, u64 b) {
    u64 r; asm("add.rn.f32x2 %0,%1,%2;" : "=l"(r) : "l"(a), "l"(b)); return r;
}
__device__ __forceinline__ u64 subx2(u64 a, u64 b) {
    u64 r; asm("sub.rn.f32x2 %0,%1,%2;" : "=l"(r) : "l"(a), "l"(b)); return r;
}
__device__ __forceinline__ u64 mulx2(u64 a, u64 b) {
    u64 r; asm("mul.rn.f32x2 %0,%1,%2;" : "=l"(r) : "l"(a), "l"(b)); return r;
}
__device__ __forceinline__ u64 pk(float lo, float hi) {
    u64 r; asm("mov.b64 %0,{%1,%2};" : "=l"(r) : "f"(lo), "f"(hi)); return r;
}
__device__ __forceinline__ void upk(float& lo, float& hi, u64 v) {
    asm("mov.b64 {%0,%1},%2;" : "=f"(lo), "=f"(hi) : "l"(v));
}

#define BFLY(A, B) { u64 _a = (A), _b = (B); (A) = addx2(_a, _b); (B) = subx2(_a, _b); }

// 4 local stages over 16-reg array (reg-index bits 0..3)
#define LOCAL4(y) \
    { _Pragma("unroll") for (int s = 1; s < 16; s <<= 1) { \
        _Pragma("unroll") for (int j = 0; j < 16; ++j) \
            if ((j & s) == 0) BFLY(y[j], y[j | s]); } }

// cross-thread stage (d0 bit = lane bit 4), phase-1 only
#define CROSS(y, q) \
    { _Pragma("unroll") for (int i = 0; i < 16; ++i) { \
        u64 _o = __shfl_xor_sync(0xffffffffu, y[i], 16); \
        y[i] = (q) ? subx2(_o, y[i]) : addx2(y[i], _o); } }

// intra-register stage (pack-bit butterfly)
#define INTRA(y) \
    { _Pragma("unroll") for (int i = 0; i < 16; ++i) { \
        float _lo, _hi; upk(_lo, _hi, y[i]); \
        y[i] = pk(_lo + _hi, _lo - _hi); } }

__global__ __launch_bounds__(NTHREADS, 1)
void spinner_main_kernel(const float* __restrict__ z,
                         const float* __restrict__ d1,
                         const float* __restrict__ d2,
                         const float* __restrict__ d3,
                         const float* __restrict__ bia,
                         const float* __restrict__ sldj_in,
                         float* __restrict__ out)
{
    extern __shared__ u64 sm[];
    const int tid = threadIdx.x;
    const int bid = blockIdx.x;

    // ---- block 0: sldj ----
    if (bid == 0) {
        float* red = (float*)sm;
        float s = 0.f;
        #pragma unroll
        for (int r = 0; r < 2; ++r) {
            int i = tid + r * NTHREADS;
            s += logf(fabsf(d1[i])) + logf(fabsf(d2[i])) + logf(fabsf(d3[i]));
        }
        red[tid] = s;
        __syncthreads();
        #pragma unroll
        for (int w = 512; w > 0; w >>= 1) {
            if (tid < w) red[tid] += red[tid + w];
            __syncthreads();
        }
        float ld = red[0];
        if (tid < KK * MM)
            out[(size_t)KK * MM * DD * TT + tid] = sldj_in[tid] + ld;
        return;
    }

    float* xcf = (float*)sm;                 // exchange, float-granular

    const int tile = bid - 1;
    const int km = tile >> 3;
    const int t0 = (tile & 7) * TTILE;
    const int t  = tid & 15;
    const int q  = (tid >> 4) & 1;
    const int u  = tid >> 5;                 // 0..31

    const float* zin = z + (size_t)km * (DD * TT) + (t0 + t);
    u64 y[16];

    // ---- PREFETCH raw z (phase-1: h=u, dlow = 2i+q packed with +32) ----
    #pragma unroll
    for (int i = 0; i < 16; ++i) {
        int dlo = u * 64 + 2 * i + q;
        y[i] = pk(zin[(size_t)dlo * TT], zin[(size_t)(dlo + 32) * TT]);
    }

    // ---- stage scale tables (overlaps z-load latency) ----
    {
        int c = tid >> 5, p = tid & 31;
        int d = c * 64 + p;
        sm[T1O + tid] = pk(d1[d] * HNORM, d1[d + 32] * HNORM);
        sm[T3O + tid] = pk(d3[d] * HNORM, d3[d + 32] * HNORM);
        int q_ = tid >> 9, r_ = tid & 511;
        int u_ = r_ >> 4, k_ = r_ & 15;
        int dl = u_ + 32 * q_;
        sm[T2O + q_ * 600 + r_] = pk(d2[k_ * 64 + dl] * HNORM,
                                     d2[(k_ + 16) * 64 + dl] * HNORM);
        sm[TBO + q_ * 600 + r_] = pk(bia[k_ * 64 + dl],
                                     bia[(k_ + 16) * 64 + dl]);
    }
    __syncthreads();

    // ---- d1 scale ----
    #pragma unroll
    for (int i = 0; i < 16; ++i)
        y[i] = mulx2(y[i], sm[T1O + u * 32 + 2 * i + q]);

    // ---- FWHT #1 low (d0..d5): CROSS(d0) + LOCAL4(d1-d4) + INTRA(d5) ----
    CROSS(y, q); LOCAL4(y); INTRA(y);

    // exchange addressing
    float* xt = xcf + t * 2050;
    const int sq   = (2 * (u & 15) + (u >> 4)) ^ q;  // sigma0(u) ^ parity(dlow)
    const int dlow = u + 32 * q;                     // phase-2 owned d-low
    const int par  = u & 1;                          // parity(dlow) in phase-2
    float* xr = xt + dlow * 32;

    // E1-write: float (dlow=2i+q, h=u) and (dlow+32, h=u)
    #pragma unroll
    for (int i = 0; i < 16; ++i) {
        float lo, hi; upk(lo, hi, y[i]);
        xt[(2 * i + q) * 32 + sq]        = lo;
        xt[(2 * i + q + 32) * 32 + sq]   = hi;
    }
    __syncthreads();
    // E1-read: LDS.64 pairs (h=k, h=k+16) at own dlow (parity swap)
    #pragma unroll
    for (int k = 0; k < 16; ++k) {
        float2 v = *(const float2*)(xr + 2 * k);
        y[k] = par ? pk(v.y, v.x) : pk(v.x, v.y);
    }

    // ---- FWHT #1 high (d6..d10): LOCAL4(d6-d9) + INTRA(d10) ----
    LOCAL4(y); INTRA(y);

    // ---- d2 scale (phase-2 pack (d, d+1024)) ----
    {
        const u64* t2 = sm + T2O + q * 600 + u * 16;
        #pragma unroll
        for (int k = 0; k < 16; ++k) y[k] = mulx2(y[k], t2[k]);
    }

    // ---- FWHT #2 high ----
    INTRA(y); LOCAL4(y);

    // E2-write: STS.64 back to own E1-read slots (no pre-sync needed)
    #pragma unroll
    for (int k = 0; k < 16; ++k) {
        u64 v = y[k];
        if (par) v = (v >> 32) | (v << 32);
        *(u64*)(xr + 2 * k) = v;
    }
    __syncthreads();
    // E2-read: two LDS.32 per reg (phase-1 pattern)
    #pragma unroll
    for (int i = 0; i < 16; ++i) {
        float lo = xt[(2 * i + q) * 32 + sq];
        float hi = xt[(2 * i + q + 32) * 32 + sq];
        y[i] = pk(lo, hi);
    }

    // ---- FWHT #2 low ----
    INTRA(y); LOCAL4(y); CROSS(y, q);

    // ---- d3 scale ----
    #pragma unroll
    for (int i = 0; i < 16; ++i)
        y[i] = mulx2(y[i], sm[T3O + u * 32 + 2 * i + q]);

    // ---- FWHT #3 low ----
    CROSS(y, q); LOCAL4(y); INTRA(y);

    // E3-write (own E2-read slots: no pre-sync)
    #pragma unroll
    for (int i = 0; i < 16; ++i) {
        float lo, hi; upk(lo, hi, y[i]);
        xt[(2 * i + q) * 32 + sq]        = lo;
        xt[(2 * i + q + 32) * 32 + sq]   = hi;
    }
    __syncthreads();
    // E3-read
    #pragma unroll
    for (int k = 0; k < 16; ++k) {
        float2 v = *(const float2*)(xr + 2 * k);
        y[k] = par ? pk(v.y, v.x) : pk(v.x, v.y);
    }

    // ---- FWHT #3 high ----
    LOCAL4(y); INTRA(y);

    // ---- bias + store (rows k*64+dlow and (k+16)*64+dlow) ----
    {
        float* zout = out + (size_t)km * (DD * TT) + (t0 + t);
        const u64* tb = sm + TBO + q * 600 + u * 16;
        #pragma unroll
        for (int k = 0; k < 16; ++k) {
            u64 r_ = addx2(y[k], tb[k]);
            float lo, hi; upk(lo, hi, r_);
            zout[(size_t)(k * 64 + dlow) * TT]        = lo;
            zout[(size_t)((k + 16) * 64 + dlow) * TT] = hi;
        }
    }
}

extern "C" void kernel_launch(void* const* d_in, const int* in_sizes, int n_in,
                              void* d_out, int out_size)
{
    (void)in_sizes; (void)n_in; (void)out_size;
    const float* z    = (const float*)d_in[0];
    const float* d1   = (const float*)d_in[1];
    const float* d2   = (const float*)d_in[2];
    const float* d3   = (const float*)d_in[3];
    const float* bia  = (const float*)d_in[4];
    const float* sldj = (const float*)d_in[5];
    float* out = (float*)d_out;

    cudaFuncSetAttribute(spinner_main_kernel,
                         cudaFuncAttributeMaxDynamicSharedMemorySize, SMEM_BYTES);

    // grid: 1 sldj block + 1024 tile blocks
    spinner_main_kernel<<<NTILES + 1, NTHREADS, SMEM_BYTES>>>(
        z, d1, d2, d3, bia, sldj, out);
}